// round 2
// baseline (speedup 1.0000x reference)
#include <cuda_runtime.h>

#define NB   32     // batch
#define SEQL 256    // L
#define NH   128    // hidden
#define NVOC 10
#define NDIG 128    // digits = L/2
#define NT   129    // digits + 1
#define TP   144    // padded time row: [0,4) zero halo, [4,133) data, [133,144) zero halo
#define HALO 4
#define NITER 131   // digits + 3
#define NG   4      // channel groups (CTAs) per batch
#define OC   32     // output channels per CTA
#define NTHREADS 512

// Double-buffered hidden state in global (L2-resident, 4.7 MB), halos stay zero.
__device__ float g_h[2][NB][NH][TP];

// ---------- packed f32x2 helpers (Blackwell dual-rate fp32) ----------
__device__ __forceinline__ unsigned long long pk2(float a, float b){
    unsigned long long r;
    asm("mov.b64 %0, {%1, %2};" : "=l"(r) : "f"(a), "f"(b));
    return r;
}
__device__ __forceinline__ void fma2(unsigned long long& d, unsigned long long a, unsigned long long b){
    asm("fma.rn.f32x2 %0, %1, %2, %0;" : "+l"(d) : "l"(a), "l"(b));
}
__device__ __forceinline__ void unpk2(unsigned long long v, float& a, float& b){
    asm("mov.b64 {%0, %1}, %2;" : "=f"(a), "=f"(b) : "l"(v));
}

// cluster barrier: arrive has release, wait has acquire semantics (cluster scope)
#define CLUSTER_SYNC() do { \
    asm volatile("barrier.cluster.arrive.aligned;" ::: "memory"); \
    asm volatile("barrier.cluster.wait.aligned;"   ::: "memory"); } while(0)

// One residual dilated-conv iteration for this CTA's 32 output channels.
// ws2 layout (float4 view): ws2f4[(c2*3 + k)*16 + og] =
//   { w[2c2,k,og*2], w[2c2,k,og*2+1], w[2c2+1,k,og*2], w[2c2+1,k,og*2+1] }
template<int D>
__device__ __forceinline__ void conv_iter(
    const float* __restrict__ src, float* __restrict__ dst,
    float* __restrict__ hs, const float* __restrict__ ws2,
    const float* __restrict__ cb, float* __restrict__ pbuf, int obase)
{
    const int tid = threadIdx.x;

    // ---- stage full h[b] (128 x 144 fp32) from L2 into smem ----
    {
        const float4* s4 = (const float4*)src;
        float4*       d4 = (float4*)hs;
        #pragma unroll
        for (int i = 0; i < (NH*TP/4)/NTHREADS; i++)     // 9 per thread
            d4[tid + i*NTHREADS] = __ldcg(s4 + tid + i*NTHREADS);
    }
    __syncthreads();

    const int og = tid & 15;          // 16 o-groups x 2 out-channels
    const int tt = tid >> 4;          // 32 t-tiles x 4 positions (t = 0..127)
    const int t0 = tt * 4;

    // acc[o][p]: o in {0,1} local channel, p in {0,1} time pair (t0+2p, t0+2p+1)
    unsigned long long acc00 = 0ull, acc01 = 0ull, acc10 = 0ull, acc11 = 0ull;

    // s[j] = h[c][t0 - 4 + j]; taps for output t0+i live at s[4 + i + (k-1)*D]
    const float*  hrow = hs + t0;                 // = &hs[c*TP + HALO + t0 - 4] at c=0
    const float4* wp   = (const float4*)ws2 + og; // +48 float4 per channel pair

    #pragma unroll 8
    for (int c2 = 0; c2 < NH/2; c2++){
        float4 qa0 = ((const float4*)hrow)[0];
        float4 qa1 = ((const float4*)hrow)[1];
        float4 qa2 = ((const float4*)hrow)[2];
        const float* hrowb = hrow + TP;
        float4 qb0 = ((const float4*)hrowb)[0];
        float4 qb1 = ((const float4*)hrowb)[1];
        float4 qb2 = ((const float4*)hrowb)[2];
        float4 w0 = wp[0];     // k=0: {A_o0, A_o1, B_o0, B_o1}
        float4 w1 = wp[16];    // k=1
        float4 w2 = wp[32];    // k=2

        float sa[12] = {qa0.x,qa0.y,qa0.z,qa0.w, qa1.x,qa1.y,qa1.z,qa1.w, qa2.x,qa2.y,qa2.z,qa2.w};
        float sb[12] = {qb0.x,qb0.y,qb0.z,qb0.w, qb1.x,qb1.y,qb1.z,qb1.w, qb2.x,qb2.y,qb2.z,qb2.w};

        // For D even, (base) is even -> h pairs are aligned register pairs (movs coalesce).
        #define CH_TAP(S, WO0, WO1, BASE) do {                       \
            unsigned long long h0 = pk2((S)[(BASE)],   (S)[(BASE)+1]); \
            unsigned long long h1 = pk2((S)[(BASE)+2], (S)[(BASE)+3]); \
            unsigned long long d0 = pk2((WO0), (WO0));                 \
            unsigned long long d1 = pk2((WO1), (WO1));                 \
            fma2(acc00, d0, h0); fma2(acc01, d0, h1);                  \
            fma2(acc10, d1, h0); fma2(acc11, d1, h1);                  \
        } while(0)

        CH_TAP(sa, w0.x, w0.y, 4 - D);
        CH_TAP(sa, w1.x, w1.y, 4);
        CH_TAP(sa, w2.x, w2.y, 4 + D);
        CH_TAP(sb, w0.z, w0.w, 4 - D);
        CH_TAP(sb, w1.z, w1.w, 4);
        CH_TAP(sb, w2.z, w2.w, 4 + D);
        #undef CH_TAP

        hrow += 2*TP;
        wp   += 48;
    }

    // ---- t = 128 column: partial sums (32 o x 16 chunks of 8 channels) ----
    {
        const int o  = tid >> 4;      // 0..31 (local out-channel)
        const int cg = tid & 15;      // channel chunk
        float s = 0.f;
        const float* hp = hs + (cg*8)*TP + (HALO + 128);
        #pragma unroll
        for (int j = 0; j < 8; j++){
            const int c = cg*8 + j;
            const float* wb = ws2 + ((c>>1)*3)*64 + (o>>1)*4 + ((c&1)<<1) + (o&1);
            const float* hc = hp + j*TP;
            s = fmaf(wb[0],   hc[-D], s);
            s = fmaf(wb[64],  hc[0],  s);
            s = fmaf(wb[128], hc[D],  s);
        }
        pbuf[(tid >> 4)*16 + cg] = s;
        (void)o;
    }
    __syncthreads();

    // ---- epilogue: bias + relu + residual, write slice to dst (L2) ----
    #pragma unroll
    for (int o = 0; o < 2; o++){
        const int ol = og*2 + o;
        const int cg = obase + ol;
        float r0, r1, r2, r3;
        unpk2(o ? acc10 : acc00, r0, r1);
        unpk2(o ? acc11 : acc01, r2, r3);
        const float bias = cb[ol];
        const float4 hold = *(const float4*)(hs + cg*TP + HALO + t0);
        float4 v;
        v.x = fmaxf(r0 + bias, 0.f) + hold.x;
        v.y = fmaxf(r1 + bias, 0.f) + hold.y;
        v.z = fmaxf(r2 + bias, 0.f) + hold.z;
        v.w = fmaxf(r3 + bias, 0.f) + hold.w;
        __stcg((float4*)(dst + cg*TP + HALO + t0), v);
    }

    // t=128 reduce + write (32 threads)
    if (tid < 32){
        float s = 0.f;
        #pragma unroll
        for (int j = 0; j < 16; j++) s += pbuf[tid*16 + j];
        const float v = fmaxf(s + cb[tid], 0.f) + hs[(obase + tid)*TP + (HALO + 128)];
        __stcg(dst + (obase + tid)*TP + (HALO + 128), v);
    }
}

__global__ void __cluster_dims__(NG, 1, 1) __launch_bounds__(NTHREADS, 1)
vgt_kernel(const int* __restrict__ x, const float* __restrict__ emb_w,
           const float* __restrict__ red_w, const float* __restrict__ red_b,
           const float* __restrict__ conv_w, const float* __restrict__ conv_b,
           const float* __restrict__ out_w, const float* __restrict__ out_b,
           float* __restrict__ out)
{
    extern __shared__ float sm[];
    float* hs   = sm;                      // NH*TP      = 18432 floats
    float* ws2  = hs + NH*TP;              // 64*3*64    = 12288
    float* m1   = ws2 + NH*3*OC;           // NVOC*OC    = 320
    float* m2   = m1 + NVOC*OC;            // NVOC*OC    = 320
    float* cb   = m2 + NVOC*OC;            // OC         = 32
    float* pbuf = cb + OC;                 // 512

    const int tid   = threadIdx.x;
    const int b     = blockIdx.x >> 2;
    const int g     = blockIdx.x & 3;
    const int obase = g * OC;

    // ---- prologue: interleaved weights, fused reducer tables, zero state ----
    for (int idx = tid; idx < NH/2*3*2*OC; idx += NTHREADS){   // 12288
        int c2 = idx / 192;
        int r  = idx - c2*192;
        int k  = r >> 6;
        int q  = r & 63;
        int og2 = q >> 2;
        int j   = q & 3;
        int c   = 2*c2 + (j >> 1);
        int ol  = og2*2 + (j & 1);
        ws2[idx] = conv_w[((obase + ol)*NH + c)*3 + k];
    }
    if (tid < OC) cb[tid] = conv_b[obase + tid];

    // M1[v][o] = sum_c red_w[o,c]*emb[v,c]; M2 uses red_w[o,128+c]
    for (int idx = tid; idx < NVOC*OC; idx += NTHREADS){
        int v  = idx / OC;
        int ol = idx % OC;
        const float* rw = red_w + (obase + ol)*(2*NH);
        const float* ew = emb_w + v*NH;
        float s1 = 0.f, s2 = 0.f;
        for (int c = 0; c < NH; c++){
            float e = ew[c];
            s1 = fmaf(rw[c],      e, s1);
            s2 = fmaf(rw[NH + c], e, s2);
        }
        m1[idx] = s1;
        m2[idx] = s2;
    }

    // zero both buffers of my (b, channel-slice) — establishes halos
    for (int idx = tid; idx < 2*OC*TP; idx += NTHREADS){
        int bb = idx / (OC*TP);
        int r  = idx - bb*(OC*TP);
        int c  = r / TP;
        int t  = r - c*TP;
        g_h[bb][b][obase + c][t] = 0.f;
    }
    __syncthreads();

    // ---- h0 = relu(M1[x[t]] + M2[x[t+128]] + red_b) ----
    {
        const int*   xb  = x + b*SEQL;
        const float* rbp = red_b + obase;
        for (int idx = tid; idx < OC*NDIG; idx += NTHREADS){
            int ol = idx >> 7;
            int t  = idx & 127;
            int v1 = xb[t];
            int v2 = xb[t + NDIG];
            float val = m1[v1*OC + ol] + m2[v2*OC + ol] + rbp[ol];
            g_h[0][b][obase + ol][HALO + t] = fmaxf(val, 0.f);
        }
    }
    CLUSTER_SYNC();   // arrive.release publishes our stores to cluster peers

    // ---- 131 residual conv iterations (cluster-synced, double-buffered) ----
    int cur = 0;
    #pragma unroll 1
    for (int i = 0; i < 4; i++){
        conv_iter<1>(&g_h[cur][b][0][0], &g_h[cur ^ 1][b][0][0], hs, ws2, cb, pbuf, obase);
        CLUSTER_SYNC();
        cur ^= 1;
    }
    #pragma unroll 1
    for (int i = 0; i < 4; i++){
        conv_iter<2>(&g_h[cur][b][0][0], &g_h[cur ^ 1][b][0][0], hs, ws2, cb, pbuf, obase);
        CLUSTER_SYNC();
        cur ^= 1;
    }
    #pragma unroll 1
    for (int i = 0; i < NITER - 8; i++){
        conv_iter<4>(&g_h[cur][b][0][0], &g_h[cur ^ 1][b][0][0], hs, ws2, cb, pbuf, obase);
        CLUSTER_SYNC();
        cur ^= 1;
    }

    // ---- output head: out[b,t,o] = sum_c out_w[o,c]*h[b,c,t] + out_b[o] ----
    {
        const float4* s4 = (const float4*)&g_h[cur][b][0][0];
        float4*       d4 = (float4*)hs;
        #pragma unroll
        for (int i = 0; i < (NH*TP/4)/NTHREADS; i++)
            d4[tid + i*NTHREADS] = __ldcg(s4 + tid + i*NTHREADS);
    }
    __syncthreads();

    const int tstart = g * 33;
    const int tcnt   = (NT - tstart) < 33 ? (NT - tstart) : 33;   // g=3 -> 30
    for (int idx = tid; idx < tcnt*NVOC; idx += NTHREADS){
        int t = tstart + idx / NVOC;
        int o = idx % NVOC;
        const float* wrow = out_w + o*NH;
        float s = out_b[o];
        #pragma unroll 8
        for (int c = 0; c < NH; c++)
            s = fmaf(wrow[c], hs[c*TP + HALO + t], s);
        out[(b*NT + t)*NVOC + o] = s;
    }
}

extern "C" void kernel_launch(void* const* d_in, const int* in_sizes, int n_in,
                              void* d_out, int out_size)
{
    (void)in_sizes; (void)n_in; (void)out_size;
    const int*   x      = (const int*)  d_in[0];
    const float* emb_w  = (const float*)d_in[1];
    const float* red_w  = (const float*)d_in[2];
    const float* red_b  = (const float*)d_in[3];
    const float* conv_w = (const float*)d_in[4];
    const float* conv_b = (const float*)d_in[5];
    const float* out_w  = (const float*)d_in[6];
    const float* out_b  = (const float*)d_in[7];
    float* out = (float*)d_out;

    const size_t smem = (size_t)(NH*TP + NH*3*OC + 2*NVOC*OC + OC + NTHREADS) * sizeof(float); // ~127.6 KB
    cudaFuncSetAttribute(vgt_kernel, cudaFuncAttributeMaxDynamicSharedMemorySize, (int)smem);
    vgt_kernel<<<NB*NG, NTHREADS, smem>>>(x, emb_w, red_w, red_b,
                                          conv_w, conv_b, out_w, out_b, out);
}

// round 3
// speedup vs baseline: 1.8358x; 1.8358x over previous
#include <cuda_runtime.h>
#include <cstdint>

#define NB   32
#define SEQL 256
#define NH   128
#define NVOC 10
#define NDIG 128
#define NT   129
#define TP   144    // [0,4) zero halo, [4,133) data (t=0..128), [133,144) zero halo
#define HALO 4
#define NITER 131
#define NG   4      // CTAs (channel groups) per batch
#define OC   32     // output channels per CTA
#define NTHREADS 512

typedef unsigned long long u64t;

// Double-buffered hidden state (L2-resident), halos stay zero.
__device__ float g_h[2][NB][NH][TP];

// ---------- packed f32x2 helpers ----------
__device__ __forceinline__ u64t pk2(float a, float b){
    u64t r; asm("mov.b64 %0, {%1, %2};" : "=l"(r) : "f"(a), "f"(b)); return r;
}
__device__ __forceinline__ void fma2(u64t& d, u64t a, u64t b){
    asm("fma.rn.f32x2 %0, %1, %2, %0;" : "+l"(d) : "l"(a), "l"(b));
}
__device__ __forceinline__ u64t add2(u64t a, u64t b){
    u64t r; asm("add.rn.f32x2 %0, %1, %2;" : "=l"(r) : "l"(a), "l"(b)); return r;
}
__device__ __forceinline__ void unpk2(u64t v, float& a, float& b){
    asm("mov.b64 {%0, %1}, %2;" : "=f"(a), "=f"(b) : "l"(v));
}
__device__ __forceinline__ void cp16(uint32_t d, const void* s){
    asm volatile("cp.async.cg.shared.global [%0], [%1], 16;" :: "r"(d), "l"(s));
}

#define CLUSTER_SYNC() do { \
    asm volatile("barrier.cluster.arrive.aligned;" ::: "memory"); \
    asm volatile("barrier.cluster.wait.aligned;"   ::: "memory"); } while(0)

// Thread layout: og = tid[0:3) (4 out-ch each), B = tid[3:5), cg = tid[5:7) (32-ch quarter),
// A = tid[7:9). t-tile tt = A*4+B (t0 = tt*8) -> within a warp t0 strides 8 floats (1 wf).
// Warps with A==3 land on all 4 SMSPs (w>>2==3 -> w in {12..15}).
template<int D>
__device__ __forceinline__ void conv_iter(
    const float* __restrict__ src, float* __restrict__ dst,
    float* __restrict__ hs, uint32_t hs_sh,
    const float* __restrict__ ws, const float* __restrict__ cb,
    u64t* __restrict__ pbuf, float* __restrict__ pbuf2, int obase)
{
    const int tid = threadIdx.x;
    const int og  = tid & 7;
    const int B   = (tid >> 3) & 3;
    const int cg  = (tid >> 5) & 3;
    const int A   = tid >> 7;
    const int lt  = (tid & 31) | (A << 5);   // index within cg-group, 0..127
    const int t0  = (A*4 + B) * 8;
    const int cbase = cg * 32;

    // ---- stage own 32-channel quarter (18 KB) from L2 via cp.async (L1 bypass) ----
    {
        const float4* sp = (const float4*)(src + cbase*TP) + lt;
        uint32_t dp = hs_sh + (uint32_t)(cbase*TP + lt*4) * 4u;
        #pragma unroll
        for (int i = 0; i < 9; i++)
            cp16(dp + i*2048u, sp + i*128);
        asm volatile("cp.async.commit_group;" ::: "memory");
        asm volatile("cp.async.wait_group 0;" ::: "memory");
    }
    asm volatile("bar.sync %0, 128;" :: "r"(1 + cg) : "memory");

    const bool sp128 = (A == 3) && (B == 3);   // these lanes also produce t=128

    u64t acc[4][4];
    #pragma unroll
    for (int oi = 0; oi < 4; oi++)
        #pragma unroll
        for (int j = 0; j < 4; j++) acc[oi][j] = 0ull;
    float accx[4] = {0.f, 0.f, 0.f, 0.f};

    // s[j] = hs[c*TP + t0 + j]  (t = t0 + j - HALO); outputs t0..t0+7 use s[4+i+(k-1)D]
    const float4* hp4 = (const float4*)(hs + cbase*TP + t0);
    const float4* wp  = (const float4*)ws + cbase*24 + og;   // ws[(c*3+k)*32 + ol]

    #pragma unroll 4
    for (int c = 0; c < 32; c++){
        float4 q0 = hp4[0], q1 = hp4[1], q2 = hp4[2], q3 = hp4[3];
        float4 w0 = wp[0], w1 = wp[8], w2 = wp[16];
        float s[16] = {q0.x,q0.y,q0.z,q0.w, q1.x,q1.y,q1.z,q1.w,
                       q2.x,q2.y,q2.z,q2.w, q3.x,q3.y,q3.z,q3.w};
        u64t hp[8];
        #pragma unroll
        for (int p = 0; p < 8; p++) hp[p] = pk2(s[2*p], s[2*p+1]);
        u64t hm[6];
        if (D == 1){
            #pragma unroll
            for (int p = 1; p < 6; p++) hm[p] = pk2(s[2*p+1], s[2*p+2]);
        }

        #define DOK(oi, wv, P, off) { u64t wd = pk2((wv),(wv)); \
            fma2(acc[oi][0], wd, (P)[(off)+0]); fma2(acc[oi][1], wd, (P)[(off)+1]); \
            fma2(acc[oi][2], wd, (P)[(off)+2]); fma2(acc[oi][3], wd, (P)[(off)+3]); }

        #define DOO(oi, c0, c1, c2) do { \
            if (D == 4)      { DOK(oi, c0, hp, 0) DOK(oi, c1, hp, 2) DOK(oi, c2, hp, 4) } \
            else if (D == 2) { DOK(oi, c0, hp, 1) DOK(oi, c1, hp, 2) DOK(oi, c2, hp, 3) } \
            else             { DOK(oi, c0, hm, 1) DOK(oi, c1, hp, 2) DOK(oi, c2, hm, 2) } \
            if (sp128) accx[oi] = fmaf((c0), s[12-D], fmaf((c1), s[12], accx[oi])); \
        } while(0)

        DOO(0, w0.x, w1.x, w2.x);
        DOO(1, w0.y, w1.y, w2.y);
        DOO(2, w0.z, w1.z, w2.z);
        DOO(3, w0.w, w1.w, w2.w);
        #undef DOO
        #undef DOK

        hp4 += TP/4;
        wp  += 24;
    }

    // ---- write partials (interleaved: [cg][ (oi*4+j)*128 + lt ]) ----
    {
        u64t* pb = pbuf + cg*2048 + lt;
        #pragma unroll
        for (int oi = 0; oi < 4; oi++)
            #pragma unroll
            for (int j = 0; j < 4; j++)
                pb[(oi*4 + j)*128] = acc[oi][j];
    }
    if (sp128){
        #pragma unroll
        for (int oi = 0; oi < 4; oi++)
            pbuf2[cg*32 + og*4 + oi] = accx[oi];
    }
    __syncthreads();

    // ---- reduce 4 cg partials, bias+relu+residual, write to dst (L2) ----
    {
        const int r   = tid;
        const int oi  = r >> 7;
        const int ltr = r & 127;
        const int o   = (r & 7)*4 + oi;
        const int tr0 = (((r >> 5) & 3)*4 + ((r >> 3) & 3)) * 8;

        float res[8];
        #pragma unroll
        for (int j = 0; j < 4; j++){
            const int k = (oi*4 + j)*128 + ltr;
            u64t v = add2(add2(pbuf[k], pbuf[2048 + k]),
                          add2(pbuf[4096 + k], pbuf[6144 + k]));
            unpk2(v, res[2*j], res[2*j+1]);
        }
        const float bias = cb[o];
        const float* hres = hs + (obase + o)*TP + HALO + tr0;
        float4 h0 = *(const float4*)hres;
        float4 h1 = *(const float4*)(hres + 4);
        float4 v0, v1;
        v0.x = fmaxf(res[0]+bias, 0.f) + h0.x;
        v0.y = fmaxf(res[1]+bias, 0.f) + h0.y;
        v0.z = fmaxf(res[2]+bias, 0.f) + h0.z;
        v0.w = fmaxf(res[3]+bias, 0.f) + h0.w;
        v1.x = fmaxf(res[4]+bias, 0.f) + h1.x;
        v1.y = fmaxf(res[5]+bias, 0.f) + h1.y;
        v1.z = fmaxf(res[6]+bias, 0.f) + h1.z;
        v1.w = fmaxf(res[7]+bias, 0.f) + h1.w;
        float* dr = dst + (obase + o)*TP + HALO + tr0;
        __stcg((float4*)dr, v0);
        __stcg((float4*)(dr + 4), v1);
    }
    // t = 128 column finalize
    if (tid < 32){
        float s = pbuf2[tid] + pbuf2[32 + tid] + pbuf2[64 + tid] + pbuf2[96 + tid];
        float v = fmaxf(s + cb[tid], 0.f) + hs[(obase + tid)*TP + HALO + 128];
        __stcg(dst + (obase + tid)*TP + HALO + 128, v);
    }
}

__global__ void __cluster_dims__(NG, 1, 1) __launch_bounds__(NTHREADS, 1)
vgt_kernel(const int* __restrict__ x, const float* __restrict__ emb_w,
           const float* __restrict__ red_w, const float* __restrict__ red_b,
           const float* __restrict__ conv_w, const float* __restrict__ conv_b,
           const float* __restrict__ out_w, const float* __restrict__ out_b,
           float* __restrict__ out)
{
    extern __shared__ __align__(16) unsigned char smraw[];
    u64t*  pbuf  = (u64t*)smraw;                    // 4*2048 u64 = 64 KB
    float* hs    = (float*)(pbuf + 8192);           // NH*TP = 18432 floats
    float* ws    = hs + NH*TP;                      // 12288
    float* cb    = ws + NH*3*OC;                    // 32
    float* m1    = cb + OC;                         // 320
    float* m2    = m1 + NVOC*OC;                    // 320
    float* pbuf2 = m2 + NVOC*OC;                    // 128

    const uint32_t hs_sh = (uint32_t)__cvta_generic_to_shared(hs);

    const int tid   = threadIdx.x;
    const int b     = blockIdx.x >> 2;
    const int g     = blockIdx.x & 3;
    const int obase = g * OC;

    // ---- prologue: weights, reducer tables, zero state ----
    for (int idx = tid; idx < NH*3*OC; idx += NTHREADS){
        int ol = idx & 31;
        int ck = idx >> 5;          // = c*3 + k
        int k  = ck % 3;
        int c  = ck / 3;
        ws[idx] = conv_w[((obase + ol)*NH + c)*3 + k];
    }
    if (tid < OC) cb[tid] = conv_b[obase + tid];

    for (int idx = tid; idx < NVOC*OC; idx += NTHREADS){
        int v  = idx / OC;
        int ol = idx % OC;
        const float* rw = red_w + (obase + ol)*(2*NH);
        const float* ew = emb_w + v*NH;
        float s1 = 0.f, s2 = 0.f;
        for (int c = 0; c < NH; c++){
            float e = ew[c];
            s1 = fmaf(rw[c],      e, s1);
            s2 = fmaf(rw[NH + c], e, s2);
        }
        m1[idx] = s1;
        m2[idx] = s2;
    }

    for (int idx = tid; idx < 2*OC*TP; idx += NTHREADS){
        int bb = idx / (OC*TP);
        int r  = idx - bb*(OC*TP);
        int c  = r / TP;
        int t  = r - c*TP;
        __stcg(&g_h[bb][b][obase + c][t], 0.f);
    }
    __syncthreads();

    // h0 = relu(M1[x[t]] + M2[x[t+128]] + red_b)
    {
        const int*   xb  = x + b*SEQL;
        const float* rbp = red_b + obase;
        for (int idx = tid; idx < OC*NDIG; idx += NTHREADS){
            int ol = idx >> 7;
            int t  = idx & 127;
            int v1 = xb[t];
            int v2 = xb[t + NDIG];
            float val = m1[v1*OC + ol] + m2[v2*OC + ol] + rbp[ol];
            __stcg(&g_h[0][b][obase + ol][HALO + t], fmaxf(val, 0.f));
        }
    }
    CLUSTER_SYNC();

    // ---- 131 residual conv iterations ----
    int cur = 0;
    #pragma unroll 1
    for (int i = 0; i < 4; i++){
        conv_iter<1>(&g_h[cur][b][0][0], &g_h[cur^1][b][0][0], hs, hs_sh, ws, cb, pbuf, pbuf2, obase);
        CLUSTER_SYNC();
        cur ^= 1;
    }
    #pragma unroll 1
    for (int i = 0; i < 4; i++){
        conv_iter<2>(&g_h[cur][b][0][0], &g_h[cur^1][b][0][0], hs, hs_sh, ws, cb, pbuf, pbuf2, obase);
        CLUSTER_SYNC();
        cur ^= 1;
    }
    #pragma unroll 1
    for (int i = 0; i < NITER - 8; i++){
        conv_iter<4>(&g_h[cur][b][0][0], &g_h[cur^1][b][0][0], hs, hs_sh, ws, cb, pbuf, pbuf2, obase);
        CLUSTER_SYNC();
        cur ^= 1;
    }

    // ---- output head ----
    {
        const float4* s4 = (const float4*)&g_h[cur][b][0][0];
        float4*       d4 = (float4*)hs;
        #pragma unroll
        for (int i = 0; i < (NH*TP/4)/NTHREADS; i++)
            d4[tid + i*NTHREADS] = __ldcg(s4 + tid + i*NTHREADS);
    }
    __syncthreads();

    const int tstart = g * 33;
    const int tcnt   = (NT - tstart) < 33 ? (NT - tstart) : 33;
    for (int idx = tid; idx < tcnt*NVOC; idx += NTHREADS){
        int t = tstart + idx / NVOC;
        int o = idx % NVOC;
        const float* wrow = out_w + o*NH;
        float s = out_b[o];
        #pragma unroll 8
        for (int c = 0; c < NH; c++)
            s = fmaf(wrow[c], hs[c*TP + HALO + t], s);
        out[(b*NT + t)*NVOC + o] = s;
    }
}

extern "C" void kernel_launch(void* const* d_in, const int* in_sizes, int n_in,
                              void* d_out, int out_size)
{
    (void)in_sizes; (void)n_in; (void)out_size;
    const int*   x      = (const int*)  d_in[0];
    const float* emb_w  = (const float*)d_in[1];
    const float* red_w  = (const float*)d_in[2];
    const float* red_b  = (const float*)d_in[3];
    const float* conv_w = (const float*)d_in[4];
    const float* conv_b = (const float*)d_in[5];
    const float* out_w  = (const float*)d_in[6];
    const float* out_b  = (const float*)d_in[7];
    float* out = (float*)d_out;

    const size_t smem = 8192*sizeof(u64t) +
        (size_t)(NH*TP + NH*3*OC + OC + 2*NVOC*OC + 128) * sizeof(float); // ~187 KB
    cudaFuncSetAttribute(vgt_kernel, cudaFuncAttributeMaxDynamicSharedMemorySize, (int)smem);
    vgt_kernel<<<NB*NG, NTHREADS, smem>>>(x, emb_w, red_w, red_b,
                                          conv_w, conv_b, out_w, out_b, out);
}